// round 14
// baseline (speedup 1.0000x reference)
#include <cuda_runtime.h>
#include <cuda_bf16.h>
#include <cstddef>

// Problem constants
#define NCH 16
#define ND  64
#define NH  96
#define NW  96
#define PLANE (NH*NW)            // 9216
#define CH_STRIDE (ND*NH*NW)     // 589824
#define KOUT 8
#define NTILE 36                 // 2 z-halves * 6 h-tiles * 3 w-tiles
#define NBLOCKS 576              // 3*6*32

// Tile geometry: 32 wide x 16 tall output, 256 threads, 4 CTAs/SM
#define TBH 16                   // output tile height
#define XROWS 20                 // extended rows (TBH+4)
#define XCOLS 36                 // extended cols (32+4)
#define NPAIR 360                // XROWS * XCOLS/2
#define GROWS 18                 // grad rows (TBH+2)
#define GPSTR 18                 // GXY/GZ4 row stride in float4 (17 pairs used)

typedef unsigned long long u64;

// ---- f32x2 packed helpers (sm_103a) ----
__device__ __forceinline__ u64 pk2(float a, float b) {
    u64 r; asm("mov.b64 %0,{%1,%2};" : "=l"(r) : "f"(a), "f"(b)); return r;
}
__device__ __forceinline__ void upk2(u64 v, float& a, float& b) {
    asm("mov.b64 {%0,%1},%2;" : "=f"(a), "=f"(b) : "l"(v));
}
__device__ __forceinline__ u64 add2(u64 a, u64 b) {
    u64 r; asm("add.rn.f32x2 %0,%1,%2;" : "=l"(r) : "l"(a), "l"(b)); return r;
}
__device__ __forceinline__ u64 mul2(u64 a, u64 b) {
    u64 r; asm("mul.rn.f32x2 %0,%1,%2;" : "=l"(r) : "l"(a), "l"(b)); return r;
}
__device__ __forceinline__ u64 fma2(u64 a, u64 b, u64 c) {
    u64 r; asm("fma.rn.f32x2 %0,%1,%2,%3;" : "=l"(r) : "l"(a), "l"(b), "l"(c)); return r;
}

__device__ float        g_part[NCH * NTILE];
__device__ int          g_idx[KOUT];
__device__ unsigned int g_ctr;    // zero-init at module load; monotonic across replays

__global__ __launch_bounds__(256, 4) void harris_kernel(const float* __restrict__ x) {
    __shared__ float2 AB[XROWS * 38];       // (A, BZ) interleaved, row stride 38
    __shared__ float4 GXY[GROWS * GPSTR];   // (gx0,gy0,gx1,gy1) per col-pair
    __shared__ float4 GZ4[GROWS * GPSTR];   // (gz0,gz1,gz2,gz3) per col-pair (dup)
    __shared__ float  RED[8];
    __shared__ double VSH[NCH];

    const int tid   = threadIdx.x;
    const int c     = blockIdx.z >> 1;
    const int zhalf = blockIdx.z & 1;
    const int h0    = blockIdx.y * TBH;
    const int w0    = blockIdx.x * 32;
    const float* xc = x + (size_t)c * CH_STRIDE;

    const int z0 = zhalf * 32;
    const int z1 = z0 + 32;
    const int s_begin = (z0 == 0) ? 0 : z0 - 1;
    const int s_end   = (z1 == ND) ? ND - 1 : z1;   // inclusive

    // ---- per-thread owned PIXEL PAIRS (even col j, j+1) of the 20x36 grid ----
    int poff[2];   // global float offset of left px (even gw), or -1 pad, -2 inactive
    int psto[2];   // AB float2 index of left px
#pragma unroll
    for (int k = 0; k < 2; k++) {
        int p = tid + k * 256;
        if (p < NPAIR) {
            int i = p / 18, m = p % 18, j = 2 * m;
            psto[k] = i*38 + j;
            int gh = h0 + i - 2, gw = w0 + j - 2;     // gw even
            poff[k] = ((unsigned)gh < (unsigned)NH && (unsigned)gw <= 94u)
                      ? gh*NW + gw : -1;
        } else { psto[k] = 0; poff[k] = -2; }
    }

    // x-depth ring per pair
    float2 xm[2], x0r[2];
#pragma unroll
    for (int k = 0; k < 2; k++) {
        xm[k] = make_float2(0.f, 0.f); x0r[k] = make_float2(0.f, 0.f);
        if (poff[k] >= 0) {
            const float2* base = reinterpret_cast<const float2*>(xc + poff[k]);
            if (s_begin - 1 >= 0) xm[k] = base[(size_t)(s_begin-1)*(PLANE/2)];
            x0r[k] = base[(size_t)s_begin*(PLANE/2)];
        }
    }

    // fused-stage ownership: 1 row fr, 2 horizontal px (col pair fp)
    const int fr = tid >> 4;          // 0..15
    const int fp = tid & 15;          // col-pair 0..15 (cols 2*fp, 2*fp+1)

    u64 A1[6], A2[6];
    const u64 ZERO2 = pk2(0.f, 0.f);
#pragma unroll
    for (int k = 0; k < 6; k++) { A1[k] = ZERO2; A2[k] = ZERO2; }
    u64 hsum2 = ZERO2;
    const u64 C1v  = pk2(1.f/19683.f, 1.f/19683.f);   // 1/27^3
    const u64 C2v  = pk2(0.04f/729.f, 0.04f/729.f);   // k/27^2
    const u64 NEG1 = pk2(-1.f, -1.f);

#define SUB2(a, b) fma2((b), NEG1, (a))

// st1: write slice T into AB (loads x(T+1) pair inline)
#define DO_ST1(T) do {                                                         \
    int t_ = (T);                                                              \
    _Pragma("unroll")                                                          \
    for (int k = 0; k < 2; k++) {                                              \
        if (k == 0 || tid < NPAIR - 256) {                                     \
            float2 xp = make_float2(0.f, 0.f);                                 \
            if (poff[k] >= 0 && t_ + 1 < ND)                                   \
                xp = reinterpret_cast<const float2*>(xc + poff[k])             \
                         [(size_t)(t_+1)*(PLANE/2)];                           \
            float4 st;                                                         \
            st.x = xm[k].x + x0r[k].x + xp.x;  st.y = xp.x - xm[k].x;          \
            st.z = xm[k].y + x0r[k].y + xp.y;  st.w = xp.y - xm[k].y;          \
            *reinterpret_cast<float4*>(AB + psto[k]) = st;                     \
            xm[k] = x0r[k]; x0r[k] = xp;                                       \
        }                                                                      \
    }                                                                          \
} while (0)

// stage2: 3 grad rows x 2 cols per thread; 6x17 = 102 active threads.
// Rolling 3-row window over 5 AB rows; writes GXY (float4) + GZ4 (dup halves).
#define DO_ST2() do {                                                          \
    if (tid < 102) {                                                           \
        int i0 = (tid / 17) * 3, jp = tid % 17, j0 = jp * 2;                   \
        float hdw[3][2], h1w[3][2], rsw[3][2];                                 \
        _Pragma("unroll")                                                      \
        for (int r = 0; r < 5; r++) {                                          \
            const float4* p = reinterpret_cast<const float4*>(AB + ((i0+r)*38 + j0)); \
            float4 u = p[0], v = p[1];                                         \
            int w = r % 3;                                                     \
            hdw[w][0] = v.x - u.x;                                             \
            hdw[w][1] = v.z - u.z;                                             \
            h1w[w][0] = u.x + 2.f*u.z + v.x;                                   \
            h1w[w][1] = u.z + 2.f*v.x + v.z;                                   \
            rsw[w][0] = u.y + u.w + v.y;                                       \
            rsw[w][1] = u.w + v.y + v.w;                                       \
            if (r >= 2) {                                                      \
                int rr = r - 2;                                                \
                int a = rr % 3, b2 = (rr+1) % 3, c2 = r % 3;                   \
                float gx0 = hdw[a][0] + 2.f*hdw[b2][0] + hdw[c2][0];           \
                float gx1 = hdw[a][1] + 2.f*hdw[b2][1] + hdw[c2][1];           \
                float gy0 = h1w[c2][0] - h1w[a][0];                            \
                float gy1 = h1w[c2][1] - h1w[a][1];                            \
                float gz0 = rsw[a][0] + rsw[b2][0] + rsw[c2][0];               \
                float gz1 = rsw[a][1] + rsw[b2][1] + rsw[c2][1];               \
                GXY[(i0+rr)*GPSTR + jp] = make_float4(gx0, gy0, gx1, gy1);     \
                float2* gz2 = reinterpret_cast<float2*>(&GZ4[(i0+rr)*GPSTR + jp]); \
                gz2[0] = make_float2(gz0, gz1);                                \
                if (jp > 0) {                                                  \
                    float2* gzp = reinterpret_cast<float2*>(&GZ4[(i0+rr)*GPSTR + jp - 1]); \
                    gzp[1] = make_float2(gz0, gz1);                            \
                }                                                              \
            }                                                                  \
        }                                                                      \
    }                                                                          \
} while (0)

    // ---- prologue: st1(s_begin), st2(s_begin) ----
    DO_ST1(s_begin);
    __syncthreads();
    DO_ST2();
    __syncthreads();

    // ================= main loop =================
    for (int s = s_begin; s <= s_end; s++) {
        const bool more = (s < s_end);

        // ---------- phase A: prefetch x(s+2), fused st3+4(s), st1-store(s+1) ----------
        float2 xpv[2];
        if (more) {
#pragma unroll
            for (int k = 0; k < 2; k++) {
                xpv[k] = make_float2(0.f, 0.f);
                if ((k == 0 || tid < NPAIR - 256) && poff[k] >= 0 && s + 2 < ND)
                    xpv[k] = reinterpret_cast<const float2*>(xc + poff[k])
                                 [(size_t)(s+2)*(PLANE/2)];
            }
        }

        // fused stage3+4 on slice s: 2 LDS.128 (GXY) + 1 LDS.128 (GZ4) per row
        {
            float l[6], rr[6];
#pragma unroll
            for (int k = 0; k < 6; k++) { l[k] = 0.f; rr[k] = 0.f; }
#pragma unroll
            for (int ri = 0; ri < 3; ri++) {
                int row = fr + ri;
                float4 q0 = GXY[row*GPSTR + fp];
                float4 q1 = GXY[row*GPSTR + fp + 1];
                float4 z4 = GZ4[row*GPSTR + fp];
                float X[4] = {q0.x, q0.z, q1.x, q1.z};
                float Y[4] = {q0.y, q0.w, q1.y, q1.w};
                float Z[4] = {z4.x, z4.y, z4.z, z4.w};
#pragma unroll
                for (int cc = 0; cc < 4; cc++) {
                    if (cc < 3) {
                        l[0] = fmaf(X[cc],X[cc],l[0]);
                        l[1] = fmaf(Y[cc],Y[cc],l[1]);
                        l[2] = fmaf(Z[cc],Z[cc],l[2]);
                        l[3] = fmaf(X[cc],Y[cc],l[3]);
                        l[4] = fmaf(X[cc],Z[cc],l[4]);
                        l[5] = fmaf(Y[cc],Z[cc],l[5]);
                    }
                    if (cc > 0) {
                        rr[0] = fmaf(X[cc],X[cc],rr[0]);
                        rr[1] = fmaf(Y[cc],Y[cc],rr[1]);
                        rr[2] = fmaf(Z[cc],Z[cc],rr[2]);
                        rr[3] = fmaf(X[cc],Y[cc],rr[3]);
                        rr[4] = fmaf(X[cc],Z[cc],rr[4]);
                        rr[5] = fmaf(Y[cc],Z[cc],rr[5]);
                    }
                }
            }
            u64 cur[6];
#pragma unroll
            for (int k = 0; k < 6; k++) cur[k] = pk2(l[k], rr[k]);

            int d = s - 1;
            if (d >= z0) {
                u64 sxx = add2(A2[0], cur[0]);
                u64 syy = add2(A2[1], cur[1]);
                u64 szz = add2(A2[2], cur[2]);
                u64 sxy = add2(A2[3], cur[3]);
                u64 sxz = add2(A2[4], cur[4]);
                u64 syz = add2(A2[5], cur[5]);
                u64 m1  = SUB2(mul2(syy, szz), mul2(syz, syz));
                u64 m2  = SUB2(mul2(sxy, szz), mul2(syz, sxz));
                u64 m3  = SUB2(mul2(sxy, syz), mul2(syy, sxz));
                u64 det = SUB2(fma2(sxx, m1, mul2(sxz, m3)), mul2(sxy, m2));
                u64 tr  = add2(add2(sxx, syy), szz);
                u64 h   = SUB2(mul2(det, C1v), mul2(mul2(tr, tr), C2v));
                hsum2 = add2(hsum2, h);
            }
#pragma unroll
            for (int k = 0; k < 6; k++) { A2[k] = add2(A1[k], cur[k]); A1[k] = cur[k]; }
        }

        // st1 stores for slice s+1 (consumes prefetched xpv)
        if (more) {
#pragma unroll
            for (int k = 0; k < 2; k++) {
                if (k == 0 || tid < NPAIR - 256) {
                    float4 st;
                    st.x = xm[k].x + x0r[k].x + xpv[k].x;  st.y = xpv[k].x - xm[k].x;
                    st.z = xm[k].y + x0r[k].y + xpv[k].y;  st.w = xpv[k].y - xm[k].y;
                    *reinterpret_cast<float4*>(AB + psto[k]) = st;
                    xm[k] = x0r[k]; x0r[k] = xpv[k];
                }
            }
        }
        __syncthreads();

        // ---------- phase B: st2(s+1) ----------
        if (more) {
            DO_ST2();
        }
        __syncthreads();
    }

    // tail: output depth ND-1 (slice at ND contributes 0)
    if (z1 == ND) {
        u64 sxx = A2[0], syy = A2[1], szz = A2[2];
        u64 sxy = A2[3], sxz = A2[4], syz = A2[5];
        u64 m1  = SUB2(mul2(syy, szz), mul2(syz, syz));
        u64 m2  = SUB2(mul2(sxy, szz), mul2(syz, sxz));
        u64 m3  = SUB2(mul2(sxy, syz), mul2(syy, sxz));
        u64 det = SUB2(fma2(sxx, m1, mul2(sxz, m3)), mul2(sxy, m2));
        u64 tr  = add2(add2(sxx, syy), szz);
        u64 h   = SUB2(mul2(det, C1v), mul2(mul2(tr, tr), C2v));
        hsum2 = add2(hsum2, h);
    }

    // ---- reduction -> g_part (non-atomic, deterministic) ----
    float ha, hb;
    upk2(hsum2, ha, hb);
    float hsum = ha + hb;
#pragma unroll
    for (int o = 16; o > 0; o >>= 1)
        hsum += __shfl_down_sync(0xffffffffu, hsum, o);
    if ((tid & 31) == 0) RED[tid >> 5] = hsum;
    __syncthreads();
    if (tid < 32) {
        float v = (tid < 8) ? RED[tid] : 0.f;
#pragma unroll
        for (int o = 4; o > 0; o >>= 1)
            v += __shfl_down_sync(0xffffffffu, v, o);
        if (tid == 0) {
            int tile_id = zhalf * 18 + blockIdx.y * 3 + blockIdx.x;
            g_part[c * NTILE + tile_id] = v;
            __threadfence();
            unsigned int cnt = atomicAdd(&g_ctr, 1u);
            RED[0] = ((cnt % NBLOCKS) == NBLOCKS - 1) ? 1.f : 0.f;
        }
    }
    __syncthreads();

    // ---- last block computes top-k (deterministic regardless of which block) ----
    if (RED[0] != 0.f) {
        __threadfence();
        if (tid < NCH) {
            double ssum = 0.0;
#pragma unroll
            for (int i = 0; i < NTILE; i++)
                ssum += (double)g_part[tid * NTILE + i];
            VSH[tid] = ssum;
        }
        __syncthreads();
        if (tid < NCH) {
            double mv = VSH[tid];
            int rank = 0;
#pragma unroll
            for (int i = 0; i < NCH; i++) {
                if (VSH[i] > mv || (VSH[i] == mv && i < tid)) rank++;
            }
            if (rank < KOUT) g_idx[rank] = tid;
        }
    }
#undef SUB2
#undef DO_ST1
#undef DO_ST2
}

// Gather: 256 threads x 4 float4; streaming hints (read-once / write-once).
__global__ __launch_bounds__(256) void gather_kernel(const float* __restrict__ x,
                                                     float* __restrict__ out) {
    const int per_ch_v = CH_STRIDE / 4;          // 147456
    const int chunks_per_ch = per_ch_v / 1024;   // 144
    int k = blockIdx.x / chunks_per_ch;
    int chunk = blockIdx.x - k * chunks_per_ch;
    int c = g_idx[k];
    const float4* src = reinterpret_cast<const float4*>(x + (size_t)c * CH_STRIDE);
    float4* dst = reinterpret_cast<float4*>(out) + (size_t)k * per_ch_v;
    int base = chunk * 1024 + threadIdx.x;
    float4 v0 = __ldcs(src + base);
    float4 v1 = __ldcs(src + base + 256);
    float4 v2 = __ldcs(src + base + 512);
    float4 v3 = __ldcs(src + base + 768);
    __stcs(dst + base,       v0);
    __stcs(dst + base + 256, v1);
    __stcs(dst + base + 512, v2);
    __stcs(dst + base + 768, v3);
}

extern "C" void kernel_launch(void* const* d_in, const int* in_sizes, int n_in,
                              void* d_out, int out_size) {
    const float* x = (const float*)d_in[0];
    float* out = (float*)d_out;

    dim3 grid(3, 6, NCH * 2);   // 576 blocks, 4 CTAs/SM, one wave
    harris_kernel<<<grid, 256>>>(x);
    const int gather_blocks = KOUT * ((CH_STRIDE / 4) / 1024);  // 1152
    gather_kernel<<<gather_blocks, 256>>>(x, out);
}

// round 15
// speedup vs baseline: 1.1341x; 1.1341x over previous
#include <cuda_runtime.h>
#include <cuda_bf16.h>
#include <cstddef>

// Problem constants
#define NCH 16
#define ND  64
#define NH  96
#define NW  96
#define PLANE (NH*NW)            // 9216
#define CH_STRIDE (ND*NH*NW)     // 589824
#define KOUT 8
#define NTILE 36                 // 2 z-halves * 6 h-tiles * 3 w-tiles
#define NBLOCKS 576              // 3*6*32

// Tile geometry: 32 wide x 16 tall output, 256 threads, 4 CTAs/SM
#define TBH 16                   // output tile height
#define XROWS 20                 // extended rows (TBH+4)
#define XCOLS 36                 // extended cols (32+4)
#define NPAIR 360                // XROWS * XCOLS/2
#define GROWS 18                 // grad rows (TBH+2)
#define GPSTR 18                 // GXY row stride in float4 (17 pairs used)
#define GSTR  36                 // GZ row stride in floats (34 used)

typedef unsigned long long u64;

// ---- f32x2 packed helpers (sm_103a) ----
__device__ __forceinline__ u64 pk2(float a, float b) {
    u64 r; asm("mov.b64 %0,{%1,%2};" : "=l"(r) : "f"(a), "f"(b)); return r;
}
__device__ __forceinline__ void upk2(u64 v, float& a, float& b) {
    asm("mov.b64 {%0,%1},%2;" : "=f"(a), "=f"(b) : "l"(v));
}
__device__ __forceinline__ u64 add2(u64 a, u64 b) {
    u64 r; asm("add.rn.f32x2 %0,%1,%2;" : "=l"(r) : "l"(a), "l"(b)); return r;
}
__device__ __forceinline__ u64 mul2(u64 a, u64 b) {
    u64 r; asm("mul.rn.f32x2 %0,%1,%2;" : "=l"(r) : "l"(a), "l"(b)); return r;
}
__device__ __forceinline__ u64 fma2(u64 a, u64 b, u64 c) {
    u64 r; asm("fma.rn.f32x2 %0,%1,%2,%3;" : "=l"(r) : "l"(a), "l"(b), "l"(c)); return r;
}

__device__ float        g_part[NCH * NTILE];
__device__ int          g_idx[KOUT];
__device__ unsigned int g_ctr;    // zero-init; monotonic across graph replays

__global__ __launch_bounds__(256, 4) void harris_kernel(const float* __restrict__ x) {
    __shared__ float2 AB[XROWS * 38];       // (A, BZ) interleaved, row stride 38
    __shared__ float4 GXY[GROWS * GPSTR];   // (gx0,gy0,gx1,gy1) per col-pair
    __shared__ float  GZ[GROWS * GSTR];
    __shared__ float  RED[8];
    __shared__ double VSH[NCH];

    const int tid   = threadIdx.x;
    const int c     = blockIdx.z >> 1;
    const int zhalf = blockIdx.z & 1;
    const int h0    = blockIdx.y * TBH;
    const int w0    = blockIdx.x * 32;
    const float* xc = x + (size_t)c * CH_STRIDE;

    const int z0 = zhalf * 32;
    const int z1 = z0 + 32;
    const int s_begin = (z0 == 0) ? 0 : z0 - 1;
    const int s_end   = (z1 == ND) ? ND - 1 : z1;   // inclusive

    // ---- per-thread owned PIXEL PAIRS (even col j, j+1) of the 20x36 grid ----
    int poff[2];   // global float offset of left px (even gw), or -1 pad, -2 inactive
    int psto[2];   // AB float2 index of left px
#pragma unroll
    for (int k = 0; k < 2; k++) {
        int p = tid + k * 256;
        if (p < NPAIR) {
            int i = p / 18, m = p % 18, j = 2 * m;
            psto[k] = i*38 + j;
            int gh = h0 + i - 2, gw = w0 + j - 2;     // gw even
            poff[k] = ((unsigned)gh < (unsigned)NH && (unsigned)gw <= 94u)
                      ? gh*NW + gw : -1;
        } else { psto[k] = 0; poff[k] = -2; }
    }

    // x-depth ring per pair
    float2 xm[2], x0r[2];
#pragma unroll
    for (int k = 0; k < 2; k++) {
        xm[k] = make_float2(0.f, 0.f); x0r[k] = make_float2(0.f, 0.f);
        if (poff[k] >= 0) {
            const float2* base = reinterpret_cast<const float2*>(xc + poff[k]);
            if (s_begin - 1 >= 0) xm[k] = base[(size_t)(s_begin-1)*(PLANE/2)];
            x0r[k] = base[(size_t)s_begin*(PLANE/2)];
        }
    }

    // fused-stage ownership: 1 row fr, 2 horizontal px (col pair fp)
    const int fr = tid >> 4;          // 0..15
    const int fp = tid & 15;          // col-pair 0..15 (cols 2*fp, 2*fp+1)

    u64 A1[6], A2[6];
    const u64 ZERO2 = pk2(0.f, 0.f);
#pragma unroll
    for (int k = 0; k < 6; k++) { A1[k] = ZERO2; A2[k] = ZERO2; }
    u64 hsum2 = ZERO2;
    const u64 C1v  = pk2(1.f/19683.f, 1.f/19683.f);   // 1/27^3
    const u64 C2v  = pk2(0.04f/729.f, 0.04f/729.f);   // k/27^2
    const u64 NEG1 = pk2(-1.f, -1.f);

#define SUB2(a, b) fma2((b), NEG1, (a))

// st1: write slice T into AB (loads x(T+1) pair inline)
#define DO_ST1(T) do {                                                         \
    int t_ = (T);                                                              \
    _Pragma("unroll")                                                          \
    for (int k = 0; k < 2; k++) {                                              \
        if (k == 0 || tid < NPAIR - 256) {                                     \
            float2 xp = make_float2(0.f, 0.f);                                 \
            if (poff[k] >= 0 && t_ + 1 < ND)                                   \
                xp = reinterpret_cast<const float2*>(xc + poff[k])             \
                         [(size_t)(t_+1)*(PLANE/2)];                           \
            float4 st;                                                         \
            st.x = xm[k].x + x0r[k].x + xp.x;  st.y = xp.x - xm[k].x;          \
            st.z = xm[k].y + x0r[k].y + xp.y;  st.w = xp.y - xm[k].y;          \
            *reinterpret_cast<float4*>(AB + psto[k]) = st;                     \
            xm[k] = x0r[k]; x0r[k] = xp;                                       \
        }                                                                      \
    }                                                                          \
} while (0)

// stage2: 3 grad rows x 2 cols per thread; 6x17 = 102 active threads.
// Rolling 3-row window over 5 AB rows; writes GXY (float4) + GZ (float2).
#define DO_ST2() do {                                                          \
    if (tid < 102) {                                                           \
        int i0 = (tid / 17) * 3, jp = tid % 17, j0 = jp * 2;                   \
        float hdw[3][2], h1w[3][2], rsw[3][2];                                 \
        _Pragma("unroll")                                                      \
        for (int r = 0; r < 5; r++) {                                          \
            const float4* p = reinterpret_cast<const float4*>(AB + ((i0+r)*38 + j0)); \
            float4 u = p[0], v = p[1];                                         \
            int w = r % 3;                                                     \
            hdw[w][0] = v.x - u.x;                                             \
            hdw[w][1] = v.z - u.z;                                             \
            h1w[w][0] = u.x + 2.f*u.z + v.x;                                   \
            h1w[w][1] = u.z + 2.f*v.x + v.z;                                   \
            rsw[w][0] = u.y + u.w + v.y;                                       \
            rsw[w][1] = u.w + v.y + v.w;                                       \
            if (r >= 2) {                                                      \
                int rr = r - 2;                                                \
                int a = rr % 3, b2 = (rr+1) % 3, c2 = r % 3;                   \
                float gx0 = hdw[a][0] + 2.f*hdw[b2][0] + hdw[c2][0];           \
                float gx1 = hdw[a][1] + 2.f*hdw[b2][1] + hdw[c2][1];           \
                float gy0 = h1w[c2][0] - h1w[a][0];                            \
                float gy1 = h1w[c2][1] - h1w[a][1];                            \
                float gz0 = rsw[a][0] + rsw[b2][0] + rsw[c2][0];               \
                float gz1 = rsw[a][1] + rsw[b2][1] + rsw[c2][1];               \
                GXY[(i0+rr)*GPSTR + jp] = make_float4(gx0, gy0, gx1, gy1);     \
                *reinterpret_cast<float2*>(GZ + (i0+rr)*GSTR + j0)             \
                    = make_float2(gz0, gz1);                                   \
            }                                                                  \
        }                                                                      \
    }                                                                          \
} while (0)

    // ---- prologue: st1(s_begin), st2(s_begin) ----
    DO_ST1(s_begin);
    __syncthreads();
    DO_ST2();
    __syncthreads();

    // ================= main loop =================
    for (int s = s_begin; s <= s_end; s++) {
        const bool more = (s < s_end);

        // ---------- phase A: prefetch x(s+2), fused st3+4(s), st1-store(s+1) ----------
        float2 xpv[2];
        if (more) {
#pragma unroll
            for (int k = 0; k < 2; k++) {
                xpv[k] = make_float2(0.f, 0.f);
                if ((k == 0 || tid < NPAIR - 256) && poff[k] >= 0 && s + 2 < ND)
                    xpv[k] = reinterpret_cast<const float2*>(xc + poff[k])
                                 [(size_t)(s+2)*(PLANE/2)];
            }
        }

        // fused stage3+4 on slice s.
        // GXY loads give natural (gx,gy) u64 pairs; per column-use:
        // fma2(v,v)->xx,yy ; fma2(v,vz)->xz,yz ; scalar zz, xy.   (R13 form)
        {
            u64 aLxxyy = ZERO2, aLxzyz = ZERO2, aRxxyy = ZERO2, aRxzyz = ZERO2;
            float aLzz = 0.f, aLxy = 0.f, aRzz = 0.f, aRxy = 0.f;
#pragma unroll
            for (int ri = 0; ri < 3; ri++) {
                int row = fr + ri;
                const u64* gp = reinterpret_cast<const u64*>(&GXY[row*GPSTR + fp]);
                u64 v0 = gp[0], v1 = gp[1], v2 = gp[2], v3 = gp[3];
                int bz = row*GSTR + fp*2;
                float2 za = *reinterpret_cast<const float2*>(GZ + bz);
                float2 zb = *reinterpret_cast<const float2*>(GZ + bz + 2);
                float z0v = za.x, z1v = za.y, z2v = zb.x, z3v = zb.y;
                u64 vz0 = pk2(z0v, z0v), vz1 = pk2(z1v, z1v);
                u64 vz2 = pk2(z2v, z2v), vz3 = pk2(z3v, z3v);
                float x0, y0, x1, y1, x2, y2, x3, y3;
                upk2(v0, x0, y0); upk2(v1, x1, y1);
                upk2(v2, x2, y2); upk2(v3, x3, y3);
                // left pixel: cols 0,1,2
                aLxxyy = fma2(v0, v0, fma2(v1, v1, fma2(v2, v2, aLxxyy)));
                aLxzyz = fma2(v0, vz0, fma2(v1, vz1, fma2(v2, vz2, aLxzyz)));
                aLzz = fmaf(z0v, z0v, fmaf(z1v, z1v, fmaf(z2v, z2v, aLzz)));
                aLxy = fmaf(x0, y0, fmaf(x1, y1, fmaf(x2, y2, aLxy)));
                // right pixel: cols 1,2,3
                aRxxyy = fma2(v1, v1, fma2(v2, v2, fma2(v3, v3, aRxxyy)));
                aRxzyz = fma2(v1, vz1, fma2(v2, vz2, fma2(v3, vz3, aRxzyz)));
                aRzz = fmaf(z1v, z1v, fmaf(z2v, z2v, fmaf(z3v, z3v, aRzz)));
                aRxy = fmaf(x1, y1, fmaf(x2, y2, fmaf(x3, y3, aRxy)));
            }
            // repack to (L,R)-lane form for the depth ring / det
            float sxxL, syyL, sxzL, syzL, sxxR, syyR, sxzR, syzR;
            upk2(aLxxyy, sxxL, syyL); upk2(aLxzyz, sxzL, syzL);
            upk2(aRxxyy, sxxR, syyR); upk2(aRxzyz, sxzR, syzR);
            u64 cur[6];
            cur[0] = pk2(sxxL, sxxR);
            cur[1] = pk2(syyL, syyR);
            cur[2] = pk2(aLzz, aRzz);
            cur[3] = pk2(aLxy, aRxy);
            cur[4] = pk2(sxzL, sxzR);
            cur[5] = pk2(syzL, syzR);

            int d = s - 1;
            if (d >= z0) {
                u64 sxx = add2(A2[0], cur[0]);
                u64 syy = add2(A2[1], cur[1]);
                u64 szz = add2(A2[2], cur[2]);
                u64 sxy = add2(A2[3], cur[3]);
                u64 sxz = add2(A2[4], cur[4]);
                u64 syz = add2(A2[5], cur[5]);
                u64 m1  = SUB2(mul2(syy, szz), mul2(syz, syz));
                u64 m2  = SUB2(mul2(sxy, szz), mul2(syz, sxz));
                u64 m3  = SUB2(mul2(sxy, syz), mul2(syy, sxz));
                u64 det = SUB2(fma2(sxx, m1, mul2(sxz, m3)), mul2(sxy, m2));
                u64 tr  = add2(add2(sxx, syy), szz);
                u64 h   = SUB2(mul2(det, C1v), mul2(mul2(tr, tr), C2v));
                hsum2 = add2(hsum2, h);
            }
#pragma unroll
            for (int k = 0; k < 6; k++) { A2[k] = add2(A1[k], cur[k]); A1[k] = cur[k]; }
        }

        // st1 stores for slice s+1 (consumes prefetched xpv)
        if (more) {
#pragma unroll
            for (int k = 0; k < 2; k++) {
                if (k == 0 || tid < NPAIR - 256) {
                    float4 st;
                    st.x = xm[k].x + x0r[k].x + xpv[k].x;  st.y = xpv[k].x - xm[k].x;
                    st.z = xm[k].y + x0r[k].y + xpv[k].y;  st.w = xpv[k].y - xm[k].y;
                    *reinterpret_cast<float4*>(AB + psto[k]) = st;
                    xm[k] = x0r[k]; x0r[k] = xpv[k];
                }
            }
        }
        __syncthreads();

        // ---------- phase B: st2(s+1) ----------
        if (more) {
            DO_ST2();
        }
        __syncthreads();
    }

    // tail: output depth ND-1 (slice at ND contributes 0)
    if (z1 == ND) {
        u64 sxx = A2[0], syy = A2[1], szz = A2[2];
        u64 sxy = A2[3], sxz = A2[4], syz = A2[5];
        u64 m1  = SUB2(mul2(syy, szz), mul2(syz, syz));
        u64 m2  = SUB2(mul2(sxy, szz), mul2(syz, sxz));
        u64 m3  = SUB2(mul2(sxy, syz), mul2(syy, sxz));
        u64 det = SUB2(fma2(sxx, m1, mul2(sxz, m3)), mul2(sxy, m2));
        u64 tr  = add2(add2(sxx, syy), szz);
        u64 h   = SUB2(mul2(det, C1v), mul2(mul2(tr, tr), C2v));
        hsum2 = add2(hsum2, h);
    }

    // ---- reduction -> g_part + last-block top-k ----
    float ha, hb;
    upk2(hsum2, ha, hb);
    float hsum = ha + hb;
#pragma unroll
    for (int o = 16; o > 0; o >>= 1)
        hsum += __shfl_down_sync(0xffffffffu, hsum, o);
    if ((tid & 31) == 0) RED[tid >> 5] = hsum;
    __syncthreads();
    if (tid < 32) {
        float v = (tid < 8) ? RED[tid] : 0.f;
#pragma unroll
        for (int o = 4; o > 0; o >>= 1)
            v += __shfl_down_sync(0xffffffffu, v, o);
        if (tid == 0) {
            int tile_id = zhalf * 18 + blockIdx.y * 3 + blockIdx.x;
            g_part[c * NTILE + tile_id] = v;
            __threadfence();
            unsigned int cnt = atomicAdd(&g_ctr, 1u);
            RED[0] = ((cnt % NBLOCKS) == NBLOCKS - 1) ? 1.f : 0.f;
        }
    }
    __syncthreads();

    // last-arriving block computes top-k (result deterministic)
    if (RED[0] != 0.f) {
        __threadfence();
        if (tid < NCH) {
            double ssum = 0.0;
#pragma unroll
            for (int i = 0; i < NTILE; i++)
                ssum += (double)g_part[tid * NTILE + i];
            VSH[tid] = ssum;
        }
        __syncthreads();
        if (tid < NCH) {
            double mv = VSH[tid];
            int rank = 0;
#pragma unroll
            for (int i = 0; i < NCH; i++) {
                if (VSH[i] > mv || (VSH[i] == mv && i < tid)) rank++;
            }
            if (rank < KOUT) g_idx[rank] = tid;
        }
    }
#undef SUB2
#undef DO_ST1
#undef DO_ST2
}

// Gather: 256 threads x 4 float4; streaming hints (read-once / write-once).
__global__ __launch_bounds__(256) void gather_kernel(const float* __restrict__ x,
                                                     float* __restrict__ out) {
    const int per_ch_v = CH_STRIDE / 4;          // 147456
    const int chunks_per_ch = per_ch_v / 1024;   // 144
    int k = blockIdx.x / chunks_per_ch;
    int chunk = blockIdx.x - k * chunks_per_ch;
    int c = g_idx[k];
    const float4* src = reinterpret_cast<const float4*>(x + (size_t)c * CH_STRIDE);
    float4* dst = reinterpret_cast<float4*>(out) + (size_t)k * per_ch_v;
    int base = chunk * 1024 + threadIdx.x;
    float4 v0 = __ldcs(src + base);
    float4 v1 = __ldcs(src + base + 256);
    float4 v2 = __ldcs(src + base + 512);
    float4 v3 = __ldcs(src + base + 768);
    __stcs(dst + base,       v0);
    __stcs(dst + base + 256, v1);
    __stcs(dst + base + 512, v2);
    __stcs(dst + base + 768, v3);
}

extern "C" void kernel_launch(void* const* d_in, const int* in_sizes, int n_in,
                              void* d_out, int out_size) {
    const float* x = (const float*)d_in[0];
    float* out = (float*)d_out;

    dim3 grid(3, 6, NCH * 2);   // 576 blocks, 4 CTAs/SM, one wave
    harris_kernel<<<grid, 256>>>(x);
    const int gather_blocks = KOUT * ((CH_STRIDE / 4) / 1024);  // 1152
    gather_kernel<<<gather_blocks, 256>>>(x, out);
}

// round 16
// speedup vs baseline: 1.1385x; 1.0039x over previous
#include <cuda_runtime.h>
#include <cuda_bf16.h>
#include <cstddef>

// Problem constants
#define NCH 16
#define ND  64
#define NH  96
#define NW  96
#define PLANE (NH*NW)            // 9216
#define CH_STRIDE (ND*NH*NW)     // 589824
#define KOUT 8
#define NTILE 36                 // 2 z-halves * 6 h-tiles * 3 w-tiles
#define NBLOCKS 576              // 3*6*32

// Tile geometry: 32 wide x 16 tall output, 256 threads, 4 CTAs/SM
#define TBH 16                   // output tile height
#define XROWS 20                 // extended rows (TBH+4)
#define XCOLS 36                 // extended cols (32+4)
#define NPAIR 360                // XROWS * XCOLS/2
#define GROWS 18                 // grad rows (TBH+2)
#define GPSTR 18                 // GXY row stride in float4 (17 pairs used)
#define GSTR  36                 // GZ row stride in floats (34 used)

typedef unsigned long long u64;

// ---- f32x2 packed helpers (sm_103a) ----
__device__ __forceinline__ u64 pk2(float a, float b) {
    u64 r; asm("mov.b64 %0,{%1,%2};" : "=l"(r) : "f"(a), "f"(b)); return r;
}
__device__ __forceinline__ void upk2(u64 v, float& a, float& b) {
    asm("mov.b64 {%0,%1},%2;" : "=f"(a), "=f"(b) : "l"(v));
}
__device__ __forceinline__ u64 add2(u64 a, u64 b) {
    u64 r; asm("add.rn.f32x2 %0,%1,%2;" : "=l"(r) : "l"(a), "l"(b)); return r;
}
__device__ __forceinline__ u64 mul2(u64 a, u64 b) {
    u64 r; asm("mul.rn.f32x2 %0,%1,%2;" : "=l"(r) : "l"(a), "l"(b)); return r;
}
__device__ __forceinline__ u64 fma2(u64 a, u64 b, u64 c) {
    u64 r; asm("fma.rn.f32x2 %0,%1,%2,%3;" : "=l"(r) : "l"(a), "l"(b), "l"(c)); return r;
}

__device__ float        g_part[NCH * NTILE];
__device__ int          g_idx[KOUT];
__device__ unsigned int g_ctr;    // zero-init; monotonic across graph replays

__global__ __launch_bounds__(256, 4) void harris_kernel(const float* __restrict__ x) {
    __shared__ float2 AB[XROWS * 38];       // (A, BZ) interleaved, row stride 38
    __shared__ float4 GXY[GROWS * GPSTR];   // (gx0,gy0,gx1,gy1) per col-pair
    __shared__ float  GZ[GROWS * GSTR];
    __shared__ float  RED[8];
    __shared__ double VSH[NCH];

    const int tid   = threadIdx.x;
    const int c     = blockIdx.z >> 1;
    const int zhalf = blockIdx.z & 1;
    const int h0    = blockIdx.y * TBH;
    const int w0    = blockIdx.x * 32;
    const float* xc = x + (size_t)c * CH_STRIDE;

    const int z0 = zhalf * 32;
    const int z1 = z0 + 32;
    const int s_begin = (z0 == 0) ? 0 : z0 - 1;
    const int s_end   = (z1 == ND) ? ND - 1 : z1;   // inclusive

    // ---- per-thread owned PIXEL PAIRS (even col j, j+1) of the 20x36 grid ----
    int poff[2];   // global float offset of left px (even gw), or -1 pad, -2 inactive
    int psto[2];   // AB float2 index of left px
#pragma unroll
    for (int k = 0; k < 2; k++) {
        int p = tid + k * 256;
        if (p < NPAIR) {
            int i = p / 18, m = p % 18, j = 2 * m;
            psto[k] = i*38 + j;
            int gh = h0 + i - 2, gw = w0 + j - 2;     // gw even
            poff[k] = ((unsigned)gh < (unsigned)NH && (unsigned)gw <= 94u)
                      ? gh*NW + gw : -1;
        } else { psto[k] = 0; poff[k] = -2; }
    }

    // x-depth ring per pair
    float2 xm[2], x0r[2];
#pragma unroll
    for (int k = 0; k < 2; k++) {
        xm[k] = make_float2(0.f, 0.f); x0r[k] = make_float2(0.f, 0.f);
        if (poff[k] >= 0) {
            const float2* base = reinterpret_cast<const float2*>(xc + poff[k]);
            if (s_begin - 1 >= 0) xm[k] = base[(size_t)(s_begin-1)*(PLANE/2)];
            x0r[k] = base[(size_t)s_begin*(PLANE/2)];
        }
    }

    // fused-stage ownership: 1 row fr, 2 horizontal px (col pair fp)
    const int fr = tid >> 4;          // 0..15
    const int fp = tid & 15;          // col-pair 0..15 (cols 2*fp, 2*fp+1)

    u64 A1[6], A2[6];
    const u64 ZERO2 = pk2(0.f, 0.f);
#pragma unroll
    for (int k = 0; k < 6; k++) { A1[k] = ZERO2; A2[k] = ZERO2; }
    u64 hsum2 = ZERO2;
    const u64 C1v  = pk2(1.f/19683.f, 1.f/19683.f);   // 1/27^3
    const u64 C2v  = pk2(0.04f/729.f, 0.04f/729.f);   // k/27^2
    const u64 NEG1 = pk2(-1.f, -1.f);

#define SUB2(a, b) fma2((b), NEG1, (a))

// st1: write slice T into AB (loads x(T+1) pair inline)
#define DO_ST1(T) do {                                                         \
    int t_ = (T);                                                              \
    _Pragma("unroll")                                                          \
    for (int k = 0; k < 2; k++) {                                              \
        if (k == 0 || tid < NPAIR - 256) {                                     \
            float2 xp = make_float2(0.f, 0.f);                                 \
            if (poff[k] >= 0 && t_ + 1 < ND)                                   \
                xp = reinterpret_cast<const float2*>(xc + poff[k])             \
                         [(size_t)(t_+1)*(PLANE/2)];                           \
            float4 st;                                                         \
            st.x = xm[k].x + x0r[k].x + xp.x;  st.y = xp.x - xm[k].x;          \
            st.z = xm[k].y + x0r[k].y + xp.y;  st.w = xp.y - xm[k].y;          \
            *reinterpret_cast<float4*>(AB + psto[k]) = st;                     \
            xm[k] = x0r[k]; x0r[k] = xp;                                       \
        }                                                                      \
    }                                                                          \
} while (0)

// stage2: 3 grad rows x 2 cols per thread; 6x17 = 102 active threads.
// Rolling 3-row window over 5 AB rows; writes GXY (float4) + GZ (float2).
#define DO_ST2() do {                                                          \
    if (tid < 102) {                                                           \
        int i0 = (tid / 17) * 3, jp = tid % 17, j0 = jp * 2;                   \
        float hdw[3][2], h1w[3][2], rsw[3][2];                                 \
        _Pragma("unroll")                                                      \
        for (int r = 0; r < 5; r++) {                                          \
            const float4* p = reinterpret_cast<const float4*>(AB + ((i0+r)*38 + j0)); \
            float4 u = p[0], v = p[1];                                         \
            int w = r % 3;                                                     \
            hdw[w][0] = v.x - u.x;                                             \
            hdw[w][1] = v.z - u.z;                                             \
            h1w[w][0] = u.x + 2.f*u.z + v.x;                                   \
            h1w[w][1] = u.z + 2.f*v.x + v.z;                                   \
            rsw[w][0] = u.y + u.w + v.y;                                       \
            rsw[w][1] = u.w + v.y + v.w;                                       \
            if (r >= 2) {                                                      \
                int rr = r - 2;                                                \
                int a = rr % 3, b2 = (rr+1) % 3, c2 = r % 3;                   \
                float gx0 = hdw[a][0] + 2.f*hdw[b2][0] + hdw[c2][0];           \
                float gx1 = hdw[a][1] + 2.f*hdw[b2][1] + hdw[c2][1];           \
                float gy0 = h1w[c2][0] - h1w[a][0];                            \
                float gy1 = h1w[c2][1] - h1w[a][1];                            \
                float gz0 = rsw[a][0] + rsw[b2][0] + rsw[c2][0];               \
                float gz1 = rsw[a][1] + rsw[b2][1] + rsw[c2][1];               \
                GXY[(i0+rr)*GPSTR + jp] = make_float4(gx0, gy0, gx1, gy1);     \
                *reinterpret_cast<float2*>(GZ + (i0+rr)*GSTR + j0)             \
                    = make_float2(gz0, gz1);                                   \
            }                                                                  \
        }                                                                      \
    }                                                                          \
} while (0)

    // ---- prologue: st1(s_begin), st2(s_begin) ----
    DO_ST1(s_begin);
    __syncthreads();
    DO_ST2();
    __syncthreads();

    // ================= main loop =================
    for (int s = s_begin; s <= s_end; s++) {
        const bool more = (s < s_end);

        // ---------- phase A: prefetch x(s+2), fused st3+4(s), st1-store(s+1) ----------
        float2 xpv[2];
        if (more) {
#pragma unroll
            for (int k = 0; k < 2; k++) {
                xpv[k] = make_float2(0.f, 0.f);
                if ((k == 0 || tid < NPAIR - 256) && poff[k] >= 0 && s + 2 < ND)
                    xpv[k] = reinterpret_cast<const float2*>(xc + poff[k])
                                 [(size_t)(s+2)*(PLANE/2)];
            }
        }

        // fused stage3+4 on slice s.
        // GXY loads give natural (gx,gy) u64 pairs; per column-use:
        // fma2(v,v)->xx,yy ; fma2(v,vz)->xz,yz ; scalar zz, xy.
        {
            u64 aLxxyy = ZERO2, aLxzyz = ZERO2, aRxxyy = ZERO2, aRxzyz = ZERO2;
            float aLzz = 0.f, aLxy = 0.f, aRzz = 0.f, aRxy = 0.f;
#pragma unroll
            for (int ri = 0; ri < 3; ri++) {
                int row = fr + ri;
                const u64* gp = reinterpret_cast<const u64*>(&GXY[row*GPSTR + fp]);
                u64 v0 = gp[0], v1 = gp[1], v2 = gp[2], v3 = gp[3];
                int bz = row*GSTR + fp*2;
                float2 za = *reinterpret_cast<const float2*>(GZ + bz);
                float2 zb = *reinterpret_cast<const float2*>(GZ + bz + 2);
                float z0v = za.x, z1v = za.y, z2v = zb.x, z3v = zb.y;
                u64 vz0 = pk2(z0v, z0v), vz1 = pk2(z1v, z1v);
                u64 vz2 = pk2(z2v, z2v), vz3 = pk2(z3v, z3v);
                float x0, y0, x1, y1, x2, y2, x3, y3;
                upk2(v0, x0, y0); upk2(v1, x1, y1);
                upk2(v2, x2, y2); upk2(v3, x3, y3);
                // left pixel: cols 0,1,2
                aLxxyy = fma2(v0, v0, fma2(v1, v1, fma2(v2, v2, aLxxyy)));
                aLxzyz = fma2(v0, vz0, fma2(v1, vz1, fma2(v2, vz2, aLxzyz)));
                aLzz = fmaf(z0v, z0v, fmaf(z1v, z1v, fmaf(z2v, z2v, aLzz)));
                aLxy = fmaf(x0, y0, fmaf(x1, y1, fmaf(x2, y2, aLxy)));
                // right pixel: cols 1,2,3
                aRxxyy = fma2(v1, v1, fma2(v2, v2, fma2(v3, v3, aRxxyy)));
                aRxzyz = fma2(v1, vz1, fma2(v2, vz2, fma2(v3, vz3, aRxzyz)));
                aRzz = fmaf(z1v, z1v, fmaf(z2v, z2v, fmaf(z3v, z3v, aRzz)));
                aRxy = fmaf(x1, y1, fmaf(x2, y2, fmaf(x3, y3, aRxy)));
            }
            // repack to (L,R)-lane form for the depth ring / det
            float sxxL, syyL, sxzL, syzL, sxxR, syyR, sxzR, syzR;
            upk2(aLxxyy, sxxL, syyL); upk2(aLxzyz, sxzL, syzL);
            upk2(aRxxyy, sxxR, syyR); upk2(aRxzyz, sxzR, syzR);
            u64 cur[6];
            cur[0] = pk2(sxxL, sxxR);
            cur[1] = pk2(syyL, syyR);
            cur[2] = pk2(aLzz, aRzz);
            cur[3] = pk2(aLxy, aRxy);
            cur[4] = pk2(sxzL, sxzR);
            cur[5] = pk2(syzL, syzR);

            int d = s - 1;
            if (d >= z0) {
                u64 sxx = add2(A2[0], cur[0]);
                u64 syy = add2(A2[1], cur[1]);
                u64 szz = add2(A2[2], cur[2]);
                u64 sxy = add2(A2[3], cur[3]);
                u64 sxz = add2(A2[4], cur[4]);
                u64 syz = add2(A2[5], cur[5]);
                u64 m1  = SUB2(mul2(syy, szz), mul2(syz, syz));
                u64 m2  = SUB2(mul2(sxy, szz), mul2(syz, sxz));
                u64 m3  = SUB2(mul2(sxy, syz), mul2(syy, sxz));
                u64 det = SUB2(fma2(sxx, m1, mul2(sxz, m3)), mul2(sxy, m2));
                u64 tr  = add2(add2(sxx, syy), szz);
                u64 h   = SUB2(mul2(det, C1v), mul2(mul2(tr, tr), C2v));
                hsum2 = add2(hsum2, h);
            }
#pragma unroll
            for (int k = 0; k < 6; k++) { A2[k] = add2(A1[k], cur[k]); A1[k] = cur[k]; }
        }

        // st1 stores for slice s+1 (consumes prefetched xpv)
        if (more) {
#pragma unroll
            for (int k = 0; k < 2; k++) {
                if (k == 0 || tid < NPAIR - 256) {
                    float4 st;
                    st.x = xm[k].x + x0r[k].x + xpv[k].x;  st.y = xpv[k].x - xm[k].x;
                    st.z = xm[k].y + x0r[k].y + xpv[k].y;  st.w = xpv[k].y - xm[k].y;
                    *reinterpret_cast<float4*>(AB + psto[k]) = st;
                    xm[k] = x0r[k]; x0r[k] = xpv[k];
                }
            }
        }
        __syncthreads();

        // ---------- phase B: st2(s+1) ----------
        if (more) {
            DO_ST2();
        }
        __syncthreads();
    }

    // tail: output depth ND-1 (slice at ND contributes 0)
    if (z1 == ND) {
        u64 sxx = A2[0], syy = A2[1], szz = A2[2];
        u64 sxy = A2[3], sxz = A2[4], syz = A2[5];
        u64 m1  = SUB2(mul2(syy, szz), mul2(syz, syz));
        u64 m2  = SUB2(mul2(sxy, szz), mul2(syz, sxz));
        u64 m3  = SUB2(mul2(sxy, syz), mul2(syy, sxz));
        u64 det = SUB2(fma2(sxx, m1, mul2(sxz, m3)), mul2(sxy, m2));
        u64 tr  = add2(add2(sxx, syy), szz);
        u64 h   = SUB2(mul2(det, C1v), mul2(mul2(tr, tr), C2v));
        hsum2 = add2(hsum2, h);
    }

    // ---- reduction -> g_part + last-block top-k ----
    float ha, hb;
    upk2(hsum2, ha, hb);
    float hsum = ha + hb;
#pragma unroll
    for (int o = 16; o > 0; o >>= 1)
        hsum += __shfl_down_sync(0xffffffffu, hsum, o);
    if ((tid & 31) == 0) RED[tid >> 5] = hsum;
    __syncthreads();
    if (tid < 32) {
        float v = (tid < 8) ? RED[tid] : 0.f;
#pragma unroll
        for (int o = 4; o > 0; o >>= 1)
            v += __shfl_down_sync(0xffffffffu, v, o);
        if (tid == 0) {
            int tile_id = zhalf * 18 + blockIdx.y * 3 + blockIdx.x;
            g_part[c * NTILE + tile_id] = v;
            __threadfence();
            unsigned int cnt = atomicAdd(&g_ctr, 1u);
            RED[0] = ((cnt % NBLOCKS) == NBLOCKS - 1) ? 1.f : 0.f;
        }
    }
    __syncthreads();

    // last-arriving block computes top-k (result deterministic)
    if (RED[0] != 0.f) {
        __threadfence();
        if (tid < NCH) {
            double ssum = 0.0;
#pragma unroll
            for (int i = 0; i < NTILE; i++)
                ssum += (double)g_part[tid * NTILE + i];
            VSH[tid] = ssum;
        }
        __syncthreads();
        if (tid < NCH) {
            double mv = VSH[tid];
            int rank = 0;
#pragma unroll
            for (int i = 0; i < NCH; i++) {
                if (VSH[i] > mv || (VSH[i] == mv && i < tid)) rank++;
            }
            if (rank < KOUT) g_idx[rank] = tid;
        }
    }
#undef SUB2
#undef DO_ST1
#undef DO_ST2
}

// Gather: 256 threads x 4 float4; streaming reads, write-through stores
// (no L2 write-allocate on the pure output stream).
__global__ __launch_bounds__(256) void gather_kernel(const float* __restrict__ x,
                                                     float* __restrict__ out) {
    const int per_ch_v = CH_STRIDE / 4;          // 147456
    const int chunks_per_ch = per_ch_v / 1024;   // 144
    int k = blockIdx.x / chunks_per_ch;
    int chunk = blockIdx.x - k * chunks_per_ch;
    int c = g_idx[k];
    const float4* src = reinterpret_cast<const float4*>(x + (size_t)c * CH_STRIDE);
    float4* dst = reinterpret_cast<float4*>(out) + (size_t)k * per_ch_v;
    int base = chunk * 1024 + threadIdx.x;
    float4 v0 = __ldcs(src + base);
    float4 v1 = __ldcs(src + base + 256);
    float4 v2 = __ldcs(src + base + 512);
    float4 v3 = __ldcs(src + base + 768);
    __stwt(dst + base,       v0);
    __stwt(dst + base + 256, v1);
    __stwt(dst + base + 512, v2);
    __stwt(dst + base + 768, v3);
}

extern "C" void kernel_launch(void* const* d_in, const int* in_sizes, int n_in,
                              void* d_out, int out_size) {
    const float* x = (const float*)d_in[0];
    float* out = (float*)d_out;

    dim3 grid(3, 6, NCH * 2);   // 576 blocks, 4 CTAs/SM, one wave
    harris_kernel<<<grid, 256>>>(x);
    const int gather_blocks = KOUT * ((CH_STRIDE / 4) / 1024);  // 1152
    gather_kernel<<<gather_blocks, 256>>>(x, out);
}